// round 1
// baseline (speedup 1.0000x reference)
#include <cuda_runtime.h>

#define NTOK 8192
#define DIM  256
#define BM   64
#define BK   64

// Scratch for Q, K, V projections (8 MB each) — __device__ globals, no allocs.
__device__ float g_Q[NTOK * DIM];
__device__ float g_K[NTOK * DIM];
__device__ float g_V[NTOK * DIM];

// ---------------------------------------------------------------------------
// Projection GEMM: O = X @ W  for W in {WQ, WK, WV}
// grid = (8192/64, 12): blockIdx.y selects weight (y/4) and 64-col tile (y%4)
// 64x64 block tile, 256 threads, 4x4 micro-tile, K-step 32.
// ---------------------------------------------------------------------------
__global__ __launch_bounds__(256) void proj_kernel(
    const float* __restrict__ X,
    const float* __restrict__ WQ,
    const float* __restrict__ WK,
    const float* __restrict__ WV)
{
    __shared__ float As[64][36];   // pad 36 keeps float4 stores aligned, spreads banks
    __shared__ float Bs[32][64];

    const int tid  = threadIdx.x;
    const int tx   = tid & 15;
    const int ty   = tid >> 4;
    const int row0 = blockIdx.x * 64;
    const int wsel = blockIdx.y >> 2;
    const int colB = (blockIdx.y & 3) * 64;

    const float* __restrict__ W = (wsel == 0) ? WQ : (wsel == 1) ? WK : WV;
    float* __restrict__ O       = (wsel == 0) ? g_Q : (wsel == 1) ? g_K : g_V;

    float acc[4][4] = {};

    for (int k0 = 0; k0 < DIM; k0 += 32) {
        // load A tile 64x32 (float4 along k)
        #pragma unroll
        for (int it = 0; it < 2; ++it) {
            int s  = tid + it * 256;          // 512 float4 slots
            int r  = s >> 3;
            int k4 = (s & 7) * 4;
            float4 v = *reinterpret_cast<const float4*>(X + (row0 + r) * DIM + k0 + k4);
            *reinterpret_cast<float4*>(&As[r][k4]) = v;
        }
        // load B tile 32x64 (float4 along cols)
        #pragma unroll
        for (int it = 0; it < 2; ++it) {
            int s  = tid + it * 256;          // 512 float4 slots
            int kk = s >> 4;
            int c4 = (s & 15) * 4;
            float4 v = *reinterpret_cast<const float4*>(W + (k0 + kk) * DIM + colB + c4);
            *reinterpret_cast<float4*>(&Bs[kk][c4]) = v;
        }
        __syncthreads();

        #pragma unroll 8
        for (int kk = 0; kk < 32; ++kk) {
            float4 b = *reinterpret_cast<const float4*>(&Bs[kk][tx * 4]);
            float a0 = As[ty * 4 + 0][kk];
            float a1 = As[ty * 4 + 1][kk];
            float a2 = As[ty * 4 + 2][kk];
            float a3 = As[ty * 4 + 3][kk];
            acc[0][0] += a0 * b.x; acc[0][1] += a0 * b.y; acc[0][2] += a0 * b.z; acc[0][3] += a0 * b.w;
            acc[1][0] += a1 * b.x; acc[1][1] += a1 * b.y; acc[1][2] += a1 * b.z; acc[1][3] += a1 * b.w;
            acc[2][0] += a2 * b.x; acc[2][1] += a2 * b.y; acc[2][2] += a2 * b.z; acc[2][3] += a2 * b.w;
            acc[3][0] += a3 * b.x; acc[3][1] += a3 * b.y; acc[3][2] += a3 * b.z; acc[3][3] += a3 * b.w;
        }
        __syncthreads();
    }

    #pragma unroll
    for (int i = 0; i < 4; ++i) {
        float4 v = make_float4(acc[i][0], acc[i][1], acc[i][2], acc[i][3]);
        *reinterpret_cast<float4*>(O + (row0 + ty * 4 + i) * DIM + colB + tx * 4) = v;
    }
}

// ---------------------------------------------------------------------------
// Flash attention: out = softmax(Q K^T) V, fp32, no scaling.
// 128 CTAs (BM=64 queries each), 256 threads = 8 warps.
// Warp ry owns S/O rows [8*ry, 8*ry+8); lane cx owns S cols {2cx,2cx+1},
// O cols [8*cx, 8*cx+8). Row softmax reductions are whole-warp shuffles.
// ---------------------------------------------------------------------------
__device__ __forceinline__ float warp_max(float v) {
    #pragma unroll
    for (int o = 16; o > 0; o >>= 1) v = fmaxf(v, __shfl_xor_sync(0xffffffffu, v, o));
    return v;
}
__device__ __forceinline__ float warp_sum(float v) {
    #pragma unroll
    for (int o = 16; o > 0; o >>= 1) v += __shfl_xor_sync(0xffffffffu, v, o);
    return v;
}

extern __shared__ float fa_smem[];

__global__ __launch_bounds__(256, 1) void flash_kernel(float* __restrict__ out)
{
    float* QsT = fa_smem;                 // [256][64]  Q^T  (64 KB)
    float* KsT = QsT + DIM * BM;          // [256][64]  K^T  (64 KB)
    float* Vs  = KsT + DIM * BK;          // [64][256]  V    (64 KB)
    float* Ps  = Vs + BK * DIM;           // [64][64]   P    (16 KB)

    const int tid = threadIdx.x;
    const int ry  = tid >> 5;             // warp id 0..7
    const int cx  = tid & 31;             // lane
    const int q0  = blockIdx.x * BM;

    // Load Q tile transposed: QsT[k][r] = Q[q0+r][k]
    for (int s = tid; s < 64 * 64; s += 256) {   // 4096 float4 slots
        int k4 = s >> 6;
        int r  = s & 63;
        float4 v = *reinterpret_cast<const float4*>(g_Q + (q0 + r) * DIM + k4 * 4);
        QsT[(k4 * 4 + 0) * BM + r] = v.x;
        QsT[(k4 * 4 + 1) * BM + r] = v.y;
        QsT[(k4 * 4 + 2) * BM + r] = v.z;
        QsT[(k4 * 4 + 3) * BM + r] = v.w;
    }

    float acc[8][8];
    float mrow[8], lrow[8];
    #pragma unroll
    for (int i = 0; i < 8; ++i) {
        mrow[i] = -3.402823466e38f;
        lrow[i] = 0.0f;
        #pragma unroll
        for (int j = 0; j < 8; ++j) acc[i][j] = 0.0f;
    }

    for (int t = 0; t < NTOK / BK; ++t) {
        const int k0 = t * BK;
        __syncthreads();   // previous-iter reads of KsT/Vs done (also covers Q load at t=0)

        // Load K tile transposed
        for (int s = tid; s < 64 * 64; s += 256) {
            int k4 = s >> 6;
            int r  = s & 63;
            float4 v = *reinterpret_cast<const float4*>(g_K + (k0 + r) * DIM + k4 * 4);
            KsT[(k4 * 4 + 0) * BK + r] = v.x;
            KsT[(k4 * 4 + 1) * BK + r] = v.y;
            KsT[(k4 * 4 + 2) * BK + r] = v.z;
            KsT[(k4 * 4 + 3) * BK + r] = v.w;
        }
        // Load V tile row-major
        for (int s = tid; s < 64 * 64; s += 256) {
            int r  = s >> 6;
            int c4 = s & 63;
            float4 v = *reinterpret_cast<const float4*>(g_V + (k0 + r) * DIM + c4 * 4);
            *reinterpret_cast<float4*>(Vs + r * DIM + c4 * 4) = v;
        }
        __syncthreads();

        // ---- S = Q K^T : each thread 8 rows x 2 cols over K-dim 256 ----
        float sv[8][2];
        #pragma unroll
        for (int i = 0; i < 8; ++i) { sv[i][0] = 0.0f; sv[i][1] = 0.0f; }

        #pragma unroll 4
        for (int kk = 0; kk < DIM; ++kk) {
            const float4 qa = *reinterpret_cast<const float4*>(QsT + kk * BM + 8 * ry);
            const float4 qb = *reinterpret_cast<const float4*>(QsT + kk * BM + 8 * ry + 4);
            const float2 kf = *reinterpret_cast<const float2*>(KsT + kk * BK + 2 * cx);
            sv[0][0] += qa.x * kf.x; sv[0][1] += qa.x * kf.y;
            sv[1][0] += qa.y * kf.x; sv[1][1] += qa.y * kf.y;
            sv[2][0] += qa.z * kf.x; sv[2][1] += qa.z * kf.y;
            sv[3][0] += qa.w * kf.x; sv[3][1] += qa.w * kf.y;
            sv[4][0] += qb.x * kf.x; sv[4][1] += qb.x * kf.y;
            sv[5][0] += qb.y * kf.x; sv[5][1] += qb.y * kf.y;
            sv[6][0] += qb.z * kf.x; sv[6][1] += qb.z * kf.y;
            sv[7][0] += qb.w * kf.x; sv[7][1] += qb.w * kf.y;
        }

        // ---- online softmax (per-row, whole-warp reductions) ----
        #pragma unroll
        for (int i = 0; i < 8; ++i) {
            float mx = warp_max(fmaxf(sv[i][0], sv[i][1]));
            float mnew  = fmaxf(mrow[i], mx);
            float scale = __expf(mrow[i] - mnew);
            mrow[i] = mnew;
            float p0 = __expf(sv[i][0] - mnew);
            float p1 = __expf(sv[i][1] - mnew);
            float rs = warp_sum(p0 + p1);
            lrow[i] = lrow[i] * scale + rs;
            #pragma unroll
            for (int j = 0; j < 8; ++j) acc[i][j] *= scale;
            *reinterpret_cast<float2*>(Ps + (8 * ry + i) * BK + 2 * cx) = make_float2(p0, p1);
        }
        __syncwarp();   // Ps rows are warp-private: warp sync suffices

        // ---- O += P V : each thread 8 rows x 8 cols over 64 keys ----
        for (int kj = 0; kj < BK; ++kj) {
            const float4 va = *reinterpret_cast<const float4*>(Vs + kj * DIM + 8 * cx);
            const float4 vb = *reinterpret_cast<const float4*>(Vs + kj * DIM + 8 * cx + 4);
            #pragma unroll
            for (int i = 0; i < 8; ++i) {
                const float p = Ps[(8 * ry + i) * BK + kj];
                acc[i][0] += p * va.x;
                acc[i][1] += p * va.y;
                acc[i][2] += p * va.z;
                acc[i][3] += p * va.w;
                acc[i][4] += p * vb.x;
                acc[i][5] += p * vb.y;
                acc[i][6] += p * vb.z;
                acc[i][7] += p * vb.w;
            }
        }
    }

    // ---- epilogue: normalize and store ----
    #pragma unroll
    for (int i = 0; i < 8; ++i) {
        const float inv = 1.0f / lrow[i];
        float4 a = make_float4(acc[i][0] * inv, acc[i][1] * inv, acc[i][2] * inv, acc[i][3] * inv);
        float4 b = make_float4(acc[i][4] * inv, acc[i][5] * inv, acc[i][6] * inv, acc[i][7] * inv);
        float* dst = out + (q0 + 8 * ry + i) * DIM + 8 * cx;
        *reinterpret_cast<float4*>(dst)     = a;
        *reinterpret_cast<float4*>(dst + 4) = b;
    }
}

// ---------------------------------------------------------------------------

static const int FA_SMEM_BYTES = (3 * DIM * BM + BK * BK) * (int)sizeof(float); // 212992

extern "C" void kernel_launch(void* const* d_in, const int* in_sizes, int n_in,
                              void* d_out, int out_size)
{
    (void)in_sizes; (void)n_in; (void)out_size;
    const float* X  = (const float*)d_in[0];
    const float* WQ = (const float*)d_in[1];
    const float* WK = (const float*)d_in[2];
    const float* WV = (const float*)d_in[3];
    float* out = (float*)d_out;

    cudaFuncSetAttribute(flash_kernel, cudaFuncAttributeMaxDynamicSharedMemorySize, FA_SMEM_BYTES);

    proj_kernel<<<dim3(NTOK / 64, 12), 256>>>(X, WQ, WK, WV);
    flash_kernel<<<NTOK / BM, 256, FA_SMEM_BYTES>>>(out);
}

// round 2
// speedup vs baseline: 1.0022x; 1.0022x over previous
#include <cuda_runtime.h>

#define NTOK 8192
#define DIM  256
#define BM   64
#define BK   64

// Scratch for Q, K, V projections (8 MB each) — __device__ globals, no allocs.
__device__ float g_Q[NTOK * DIM];
__device__ float g_K[NTOK * DIM];
__device__ float g_V[NTOK * DIM];

// ---------------------------------------------------------------------------
// Projection GEMM: O = X @ W  for W in {WQ, WK, WV}
// grid = (8192/64, 12): blockIdx.y selects weight (y/4) and 64-col tile (y%4)
// 64x64 block tile, 256 threads, 4x4 micro-tile, K-step 32.
// ---------------------------------------------------------------------------
__global__ __launch_bounds__(256) void proj_kernel(
    const float* __restrict__ X,
    const float* __restrict__ WQ,
    const float* __restrict__ WK,
    const float* __restrict__ WV)
{
    __shared__ float As[64][36];   // pad 36 keeps float4 stores aligned, spreads banks
    __shared__ float Bs[32][64];

    const int tid  = threadIdx.x;
    const int tx   = tid & 15;
    const int ty   = tid >> 4;
    const int row0 = blockIdx.x * 64;
    const int wsel = blockIdx.y >> 2;
    const int colB = (blockIdx.y & 3) * 64;

    const float* __restrict__ W = (wsel == 0) ? WQ : (wsel == 1) ? WK : WV;
    float* __restrict__ O       = (wsel == 0) ? g_Q : (wsel == 1) ? g_K : g_V;

    float acc[4][4] = {};

    for (int k0 = 0; k0 < DIM; k0 += 32) {
        // load A tile 64x32 (float4 along k)
        #pragma unroll
        for (int it = 0; it < 2; ++it) {
            int s  = tid + it * 256;          // 512 float4 slots
            int r  = s >> 3;
            int k4 = (s & 7) * 4;
            float4 v = *reinterpret_cast<const float4*>(X + (row0 + r) * DIM + k0 + k4);
            *reinterpret_cast<float4*>(&As[r][k4]) = v;
        }
        // load B tile 32x64 (float4 along cols)
        #pragma unroll
        for (int it = 0; it < 2; ++it) {
            int s  = tid + it * 256;          // 512 float4 slots
            int kk = s >> 4;
            int c4 = (s & 15) * 4;
            float4 v = *reinterpret_cast<const float4*>(W + (k0 + kk) * DIM + colB + c4);
            *reinterpret_cast<float4*>(&Bs[kk][c4]) = v;
        }
        __syncthreads();

        #pragma unroll 8
        for (int kk = 0; kk < 32; ++kk) {
            float4 b = *reinterpret_cast<const float4*>(&Bs[kk][tx * 4]);
            float a0 = As[ty * 4 + 0][kk];
            float a1 = As[ty * 4 + 1][kk];
            float a2 = As[ty * 4 + 2][kk];
            float a3 = As[ty * 4 + 3][kk];
            acc[0][0] += a0 * b.x; acc[0][1] += a0 * b.y; acc[0][2] += a0 * b.z; acc[0][3] += a0 * b.w;
            acc[1][0] += a1 * b.x; acc[1][1] += a1 * b.y; acc[1][2] += a1 * b.z; acc[1][3] += a1 * b.w;
            acc[2][0] += a2 * b.x; acc[2][1] += a2 * b.y; acc[2][2] += a2 * b.z; acc[2][3] += a2 * b.w;
            acc[3][0] += a3 * b.x; acc[3][1] += a3 * b.y; acc[3][2] += a3 * b.z; acc[3][3] += a3 * b.w;
        }
        __syncthreads();
    }

    #pragma unroll
    for (int i = 0; i < 4; ++i) {
        float4 v = make_float4(acc[i][0], acc[i][1], acc[i][2], acc[i][3]);
        *reinterpret_cast<float4*>(O + (row0 + ty * 4 + i) * DIM + colB + tx * 4) = v;
    }
}

// ---------------------------------------------------------------------------
// Flash attention: out = softmax(Q K^T) V, fp32, no scaling.
// 128 CTAs (BM=64 queries each), 256 threads = 8 warps.
// Warp ry owns S/O rows [8*ry, 8*ry+8); lane cx owns S cols {2cx,2cx+1},
// O cols [8*cx, 8*cx+8). Row softmax reductions are whole-warp shuffles.
// ---------------------------------------------------------------------------
__device__ __forceinline__ float warp_max(float v) {
    #pragma unroll
    for (int o = 16; o > 0; o >>= 1) v = fmaxf(v, __shfl_xor_sync(0xffffffffu, v, o));
    return v;
}
__device__ __forceinline__ float warp_sum(float v) {
    #pragma unroll
    for (int o = 16; o > 0; o >>= 1) v += __shfl_xor_sync(0xffffffffu, v, o);
    return v;
}

extern __shared__ float fa_smem[];

__global__ __launch_bounds__(256, 1) void flash_kernel(float* __restrict__ out)
{
    float* QsT = fa_smem;                 // [256][64]  Q^T  (64 KB)
    float* KsT = QsT + DIM * BM;          // [256][64]  K^T  (64 KB)
    float* Vs  = KsT + DIM * BK;          // [64][256]  V    (64 KB)
    float* Ps  = Vs + BK * DIM;           // [64][64]   P    (16 KB)

    const int tid = threadIdx.x;
    const int ry  = tid >> 5;             // warp id 0..7
    const int cx  = tid & 31;             // lane
    const int q0  = blockIdx.x * BM;

    // Load Q tile transposed: QsT[k][r] = Q[q0+r][k]
    for (int s = tid; s < 64 * 64; s += 256) {   // 4096 float4 slots
        int k4 = s >> 6;
        int r  = s & 63;
        float4 v = *reinterpret_cast<const float4*>(g_Q + (q0 + r) * DIM + k4 * 4);
        QsT[(k4 * 4 + 0) * BM + r] = v.x;
        QsT[(k4 * 4 + 1) * BM + r] = v.y;
        QsT[(k4 * 4 + 2) * BM + r] = v.z;
        QsT[(k4 * 4 + 3) * BM + r] = v.w;
    }

    float acc[8][8];
    float mrow[8], lrow[8];
    #pragma unroll
    for (int i = 0; i < 8; ++i) {
        mrow[i] = -3.402823466e38f;
        lrow[i] = 0.0f;
        #pragma unroll
        for (int j = 0; j < 8; ++j) acc[i][j] = 0.0f;
    }

    for (int t = 0; t < NTOK / BK; ++t) {
        const int k0 = t * BK;
        __syncthreads();   // previous-iter reads of KsT/Vs done (also covers Q load at t=0)

        // Load K tile transposed
        for (int s = tid; s < 64 * 64; s += 256) {
            int k4 = s >> 6;
            int r  = s & 63;
            float4 v = *reinterpret_cast<const float4*>(g_K + (k0 + r) * DIM + k4 * 4);
            KsT[(k4 * 4 + 0) * BK + r] = v.x;
            KsT[(k4 * 4 + 1) * BK + r] = v.y;
            KsT[(k4 * 4 + 2) * BK + r] = v.z;
            KsT[(k4 * 4 + 3) * BK + r] = v.w;
        }
        // Load V tile row-major
        for (int s = tid; s < 64 * 64; s += 256) {
            int r  = s >> 6;
            int c4 = s & 63;
            float4 v = *reinterpret_cast<const float4*>(g_V + (k0 + r) * DIM + c4 * 4);
            *reinterpret_cast<float4*>(Vs + r * DIM + c4 * 4) = v;
        }
        __syncthreads();

        // ---- S = Q K^T : each thread 8 rows x 2 cols over K-dim 256 ----
        float sv[8][2];
        #pragma unroll
        for (int i = 0; i < 8; ++i) { sv[i][0] = 0.0f; sv[i][1] = 0.0f; }

        #pragma unroll 4
        for (int kk = 0; kk < DIM; ++kk) {
            const float4 qa = *reinterpret_cast<const float4*>(QsT + kk * BM + 8 * ry);
            const float4 qb = *reinterpret_cast<const float4*>(QsT + kk * BM + 8 * ry + 4);
            const float2 kf = *reinterpret_cast<const float2*>(KsT + kk * BK + 2 * cx);
            sv[0][0] += qa.x * kf.x; sv[0][1] += qa.x * kf.y;
            sv[1][0] += qa.y * kf.x; sv[1][1] += qa.y * kf.y;
            sv[2][0] += qa.z * kf.x; sv[2][1] += qa.z * kf.y;
            sv[3][0] += qa.w * kf.x; sv[3][1] += qa.w * kf.y;
            sv[4][0] += qb.x * kf.x; sv[4][1] += qb.x * kf.y;
            sv[5][0] += qb.y * kf.x; sv[5][1] += qb.y * kf.y;
            sv[6][0] += qb.z * kf.x; sv[6][1] += qb.z * kf.y;
            sv[7][0] += qb.w * kf.x; sv[7][1] += qb.w * kf.y;
        }

        // ---- online softmax (per-row, whole-warp reductions) ----
        #pragma unroll
        for (int i = 0; i < 8; ++i) {
            float mx = warp_max(fmaxf(sv[i][0], sv[i][1]));
            float mnew  = fmaxf(mrow[i], mx);
            float scale = __expf(mrow[i] - mnew);
            mrow[i] = mnew;
            float p0 = __expf(sv[i][0] - mnew);
            float p1 = __expf(sv[i][1] - mnew);
            float rs = warp_sum(p0 + p1);
            lrow[i] = lrow[i] * scale + rs;
            #pragma unroll
            for (int j = 0; j < 8; ++j) acc[i][j] *= scale;
            *reinterpret_cast<float2*>(Ps + (8 * ry + i) * BK + 2 * cx) = make_float2(p0, p1);
        }
        __syncwarp();   // Ps rows are warp-private: warp sync suffices

        // ---- O += P V : each thread 8 rows x 8 cols over 64 keys ----
        for (int kj = 0; kj < BK; ++kj) {
            const float4 va = *reinterpret_cast<const float4*>(Vs + kj * DIM + 8 * cx);
            const float4 vb = *reinterpret_cast<const float4*>(Vs + kj * DIM + 8 * cx + 4);
            #pragma unroll
            for (int i = 0; i < 8; ++i) {
                const float p = Ps[(8 * ry + i) * BK + kj];
                acc[i][0] += p * va.x;
                acc[i][1] += p * va.y;
                acc[i][2] += p * va.z;
                acc[i][3] += p * va.w;
                acc[i][4] += p * vb.x;
                acc[i][5] += p * vb.y;
                acc[i][6] += p * vb.z;
                acc[i][7] += p * vb.w;
            }
        }
    }

    // ---- epilogue: normalize and store ----
    #pragma unroll
    for (int i = 0; i < 8; ++i) {
        const float inv = 1.0f / lrow[i];
        float4 a = make_float4(acc[i][0] * inv, acc[i][1] * inv, acc[i][2] * inv, acc[i][3] * inv);
        float4 b = make_float4(acc[i][4] * inv, acc[i][5] * inv, acc[i][6] * inv, acc[i][7] * inv);
        float* dst = out + (q0 + 8 * ry + i) * DIM + 8 * cx;
        *reinterpret_cast<float4*>(dst)     = a;
        *reinterpret_cast<float4*>(dst + 4) = b;
    }
}

// ---------------------------------------------------------------------------

static const int FA_SMEM_BYTES = (3 * DIM * BM + BK * BK) * (int)sizeof(float); // 212992

extern "C" void kernel_launch(void* const* d_in, const int* in_sizes, int n_in,
                              void* d_out, int out_size)
{
    (void)in_sizes; (void)n_in; (void)out_size;
    const float* X  = (const float*)d_in[0];
    const float* WQ = (const float*)d_in[1];
    const float* WK = (const float*)d_in[2];
    const float* WV = (const float*)d_in[3];
    float* out = (float*)d_out;

    cudaFuncSetAttribute(flash_kernel, cudaFuncAttributeMaxDynamicSharedMemorySize, FA_SMEM_BYTES);

    proj_kernel<<<dim3(NTOK / 64, 12), 256>>>(X, WQ, WK, WV);
    flash_kernel<<<NTOK / BM, 256, FA_SMEM_BYTES>>>(out);
}